// round 17
// baseline (speedup 1.0000x reference)
#include <cuda_runtime.h>

#define NMAX 8192

// Scratch — zero-initialized at module load; clean_kernel restores zeros after
// every call (stream-ordered after reduce_kernel) so graph replays are clean.
// Arrays are 16B-aligned for vectorized cleaning.
__device__ __align__(16) int      g_cntpack[2][NMAX];  // low16: cnt, high16: pos_cnt
__device__ __align__(16) float    g_sumexp[2][NMAX];   // sum of exp(out[i]) over mask
__device__ __align__(16) float    g_poslog[2][NMAX];   // sum of out[i] over mask & pos
__device__ float    g_res;                // cross-block partial sum
__device__ unsigned g_done;               // block-completion counter

// Row-per-warp scan (locked best-measured configuration). Each warp owns 1024
// contiguous int4 quads (half a row at N=8192): row index, outs[i], targets[i],
// expf, pack computed ONCE per warp (lane-uniform). Fully coalesced LDG.128,
// front-batched x8. Loads use one base pointer + compile-time offsets so the
// quad offsets fold into LDG immediate fields (no per-load 64-bit IMAD).
__global__ void __launch_bounds__(256) main_kernel(
    const int4* __restrict__ adj,
    const float* __restrict__ outs,
    const int* __restrict__ tgt,
    int rowShift)                          // log2(quads per row)
{
    const int  gtid  = blockIdx.x * blockDim.x + threadIdx.x;
    const int  gwarp = gtid >> 5;
    const int  lane  = gtid & 31;

    const long long quadBase = (long long)gwarp << 10;          // 1024 quads/warp
    const int i      = (int)(quadBase >> rowShift);             // row (warp-uniform)
    const int cqBase = (int)(quadBase & ((1 << rowShift) - 1)); // quad offset in row

    const float o    = __ldg(&outs[i]);                         // broadcast loads
    const int   p    = (__ldg(&tgt[i]) != 0) ? 1 : 0;
    const float e    = expf(o);
    const int   pack = 1 + (p << 16);

    const int4* ptr  = adj + quadBase + lane;                   // base addr once
    const int   cTh  = (cqBase + lane) << 2;                    // column of ptr[0]

    #pragma unroll
    for (int jb = 0; jb < 4; jb++) {
        int4 vv[8];
        #pragma unroll
        for (int u = 0; u < 8; u++)
            vv[u] = __ldg(ptr + (jb * 8 + u) * 32);             // imm offsets

        #pragma unroll
        for (int u = 0; u < 8; u++) {
            int4 v = vv[u];
            if ((v.x | v.y | v.z | v.w) == 0) continue;         // ~98.5% of quads

            int c = cTh + ((jb * 8 + u) * 32 << 2);             // first column
            #pragma unroll
            for (int w = 0; w < 4; w++) {
                int val = (w == 0) ? v.x : (w == 1) ? v.y : (w == 2) ? v.z : v.w;
                int cc = c + w;
                if (val != 0 && cc != i) {
                    int side = (i < cc) ? 0 : 1;  // 0 = lower (i < k), 1 = upper
                    atomicAdd(&g_cntpack[side][cc], pack);
                    atomicAdd(&g_sumexp[side][cc], e);
                    if (p) atomicAdd(&g_poslog[side][cc], o);
                }
            }
        }
    }
}

// Direct reduce: thread t (t<K) computes the contribution of column idx[t]
// straight from the accumulators (duplicate idx entries recompute — cheap) in
// ONE flat memory round-trip: idx load, then 6 independent column loads.
// Block-reduce, last block publishes out[0].
__global__ void __launch_bounds__(256) reduce_kernel(
    float* __restrict__ out,
    const int* __restrict__ idx,
    int K)
{
    int t = blockIdx.x * blockDim.x + threadIdx.x;

    float local = 0.f;
    if (t < K) {
        int c = __ldg(&idx[t]);

        int   pack0 = g_cntpack[0][c], pack1 = g_cntpack[1][c];
        float se0 = g_sumexp[0][c], se1 = g_sumexp[1][c];
        float pl0 = g_poslog[0][c], pl1 = g_poslog[1][c];

        int cnt0 = pack0 & 0xFFFF, pc0 = pack0 >> 16;
        int cnt1 = pack1 & 0xFFFF, pc1 = pack1 >> 16;

        if (cnt0 > 0 && pc0 == 1) local += (logf(se0) - pl0) / (float)cnt0;
        if (cnt1 > 0 && pc1 == 1) local += (logf(se1) - pl1) / (float)cnt1;
    }

    #pragma unroll
    for (int s = 16; s > 0; s >>= 1)
        local += __shfl_xor_sync(0xFFFFFFFF, local, s);

    __shared__ float warpsum[8];
    int lane = threadIdx.x & 31, wid = threadIdx.x >> 5;
    if (lane == 0) warpsum[wid] = local;
    __syncthreads();
    if (wid == 0) {
        float b = (lane < 8) ? warpsum[lane] : 0.f;
        #pragma unroll
        for (int s = 4; s > 0; s >>= 1)
            b += __shfl_xor_sync(0xFFFFFFFF, b, s);
        if (lane == 0) {
            atomicAdd(&g_res, b);
            __threadfence();
            unsigned d = atomicAdd(&g_done, 1u);
            if (d == gridDim.x - 1) {
                out[0] = atomicExch(&g_res, 0.f);
                g_done = 0;
            }
        }
    }
}

// Pure-store vectorized cleanup (stream-ordered AFTER reduce_kernel). Each of
// the 6 arrays is 32KB = 2048 int4; 2048 threads each write one int4 per
// array: 6 STG.128 per thread, 8 blocks, no loads, no chains.
__global__ void __launch_bounds__(256) clean_kernel() {
    int t = blockIdx.x * blockDim.x + threadIdx.x;   // 0..2047
    const int4 z = make_int4(0, 0, 0, 0);
    reinterpret_cast<int4*>(g_cntpack[0])[t] = z;
    reinterpret_cast<int4*>(g_cntpack[1])[t] = z;
    reinterpret_cast<int4*>(g_sumexp[0])[t] = z;
    reinterpret_cast<int4*>(g_sumexp[1])[t] = z;
    reinterpret_cast<int4*>(g_poslog[0])[t] = z;
    reinterpret_cast<int4*>(g_poslog[1])[t] = z;
}

extern "C" void kernel_launch(void* const* d_in, const int* in_sizes, int n_in,
                              void* d_out, int out_size) {
    const float* outs = (const float*)d_in[0];   // outputs  [N] f32
    const int*   tgt  = (const int*)d_in[1];     // targets  [N] i32
    const int*   adj  = (const int*)d_in[2];     // node_adj [N,N] i32
    const int*   idx  = (const int*)d_in[3];     // idx_node [K] i32 (sorted)
    int N = in_sizes[0];
    int K = in_sizes[3];
    float* out = (float*)d_out;

    // quadsPerRow = N/4 is a power of two; rowShift = log2(N/4)
    int rowShift = 0;
    for (int t = N >> 2; t > 1; t >>= 1) rowShift++;

    // Each warp: 1024 quads; each block (8 warps): 8192 quads.
    long long totalQuads = ((long long)N * N) >> 2;
    int blocks = (int)(totalQuads >> 13);        // N=8192 -> 2048 blocks

    main_kernel<<<blocks, 256>>>((const int4*)adj, outs, tgt, rowShift);
    reduce_kernel<<<(K + 255) / 256, 256>>>(out, idx, K);
    clean_kernel<<<(NMAX / 4 + 255) / 256, 256>>>();   // 2048 threads
}